// round 2
// baseline (speedup 1.0000x reference)
#include <cuda_runtime.h>

// ARModel p=1, C=1, out_dim=1:
//   out[b,t,n] = (t==0) ? 0 : x[b,t-1,n] * w + bias
// Shapes: x (64, 288, 2000, 1) fp32; weights (1,1,1); bias (1,)
// Flat: out[i] = x[i - N] * w + bias for t>0, where N=2000.
// Vectorized float4: N/4 = 500 float4 per (b,t) row; t uniform per float4.

#define AR_B 64
#define AR_T 288
#define AR_N 2000
#define AR_N4 (AR_N / 4)                       // 500
#define AR_TOTAL4 (AR_B * AR_T * AR_N4)        // 9,216,000

__global__ __launch_bounds__(256) void ar_model_kernel(
    const float4* __restrict__ x4,
    const float* __restrict__ w_ptr,
    const float* __restrict__ b_ptr,
    float4* __restrict__ out4)
{
    int i = blockIdx.x * blockDim.x + threadIdx.x;
    if (i >= AR_TOTAL4) return;

    int row = i / AR_N4;          // global (b*T + t) row index
    int t   = row % AR_T;

    float4 o;
    if (t == 0) {
        o.x = 0.0f; o.y = 0.0f; o.z = 0.0f; o.w = 0.0f;
    } else {
        const float W = __ldg(w_ptr);
        const float Bi = __ldg(b_ptr);
        float4 v = x4[i - AR_N4];  // shift back one T step (N floats = N4 float4)
        o.x = fmaf(v.x, W, Bi);
        o.y = fmaf(v.y, W, Bi);
        o.z = fmaf(v.z, W, Bi);
        o.w = fmaf(v.w, W, Bi);
    }
    out4[i] = o;
}

extern "C" void kernel_launch(void* const* d_in, const int* in_sizes, int n_in,
                              void* d_out, int out_size)
{
    const float4* x4 = (const float4*)d_in[0];
    const float*  w  = (const float*)d_in[1];
    const float*  b  = (const float*)d_in[2];
    float4* out4 = (float4*)d_out;

    const int threads = 256;
    const int blocks = (AR_TOTAL4 + threads - 1) / threads;  // 36000
    ar_model_kernel<<<blocks, threads>>>(x4, w, b, out4);
}

// round 3
// speedup vs baseline: 1.0424x; 1.0424x over previous
#include <cuda_runtime.h>

// ARModel p=1, C=1, out_dim=1:
//   out[b,t,n] = (t==0) ? 0 : x[b,t-1,n] * w + bias
// Flat over float4: out4[i] = x4[i - N4]*w + bias unless t(i)==0 (then 0).
//
// R2: 4 float4 per thread, front-batched independent LDG.128s (MLP_p1=4),
// streaming cache hints (.cs) since working set (295MB) >> L2 (126MB) with
// zero reuse. Stride-S layout keeps every access 128B-coalesced.

#define AR_B 64
#define AR_T 288
#define AR_N 2000
#define AR_N4 (AR_N / 4)                       // 500
#define AR_TOTAL4 (AR_B * AR_T * AR_N4)        // 9,216,000
#define AR_UNROLL 4
#define AR_THREADS 256
#define AR_BLOCKS (AR_TOTAL4 / (AR_THREADS * AR_UNROLL))   // 9000 exact
#define AR_STRIDE (AR_BLOCKS * AR_THREADS)                 // 2,304,000

__global__ __launch_bounds__(AR_THREADS) void ar_model_kernel(
    const float4* __restrict__ x4,
    const float* __restrict__ w_ptr,
    const float* __restrict__ b_ptr,
    float4* __restrict__ out4)
{
    int base = blockIdx.x * AR_THREADS + threadIdx.x;

    const float W  = __ldg(w_ptr);
    const float Bi = __ldg(b_ptr);

    int   idx[AR_UNROLL];
    bool  live[AR_UNROLL];
    float4 v[AR_UNROLL];

    // Front-batch all loads: 4 independent LDG.128 in flight per thread.
    #pragma unroll
    for (int u = 0; u < AR_UNROLL; u++) {
        int i = base + u * AR_STRIDE;
        idx[u] = i;
        int row = i / AR_N4;           // (b*T + t)
        int t   = row % AR_T;
        live[u] = (t != 0);
        if (live[u]) {
            v[u] = __ldcs(&x4[i - AR_N4]);   // streaming read
        }
    }

    #pragma unroll
    for (int u = 0; u < AR_UNROLL; u++) {
        float4 o;
        if (live[u]) {
            o.x = fmaf(v[u].x, W, Bi);
            o.y = fmaf(v[u].y, W, Bi);
            o.z = fmaf(v[u].z, W, Bi);
            o.w = fmaf(v[u].w, W, Bi);
        } else {
            o.x = 0.0f; o.y = 0.0f; o.z = 0.0f; o.w = 0.0f;
        }
        __stcs(&out4[idx[u]], o);            // streaming write
    }
}

extern "C" void kernel_launch(void* const* d_in, const int* in_sizes, int n_in,
                              void* d_out, int out_size)
{
    const float4* x4 = (const float4*)d_in[0];
    const float*  w  = (const float*)d_in[1];
    const float*  b  = (const float*)d_in[2];
    float4* out4 = (float4*)d_out;

    ar_model_kernel<<<AR_BLOCKS, AR_THREADS>>>(x4, w, b, out4);
}